// round 13
// baseline (speedup 1.0000x reference)
#include <cuda_runtime.h>
#include <cuda_bf16.h>
#include <cstdint>
#include <cstring>

#define SEQ_LEN  131072
#define NT       128
#define NCTA     128
#define THREADS  256
#define G        64          /* chains per CTA (MMA N) */
#define CHUNK    16          /* official steps per chain */
#define WARM     8
#define STEPS    24
#define VSTRIDE  272         /* bytes per V row (bank-conflict-free) */
#define EMSTRIDE 132         /* floats per em row */
#define EMBYTES  (G * EMSTRIDE * 4)

/* dynamic smem layout */
#define SM_V0    0
#define SM_V1    17408
#define SM_EM    34816       /* 3 x EMBYTES = 3 x 33792 */
#define SM_SEL   136192      /* uchar[G*STEPS] */
#define SM_INV   137728
#define SM_FPART 137984
#define SM_LAM   138240
#define SM_RED   138496      /* float[G*8] */
#define SM_SGOLD 140544      /* double[8] */
#define SM_SLAST 140608
#define SMEM_TOTAL 140672

__device__ double   g_gold[NCTA];
__device__ double   g_tot[NCTA];
__device__ unsigned g_done = 0;

__device__ __forceinline__ void cp16(void* dst, const void* src) {
    unsigned d = (unsigned)__cvta_generic_to_shared(dst);
    asm volatile("cp.async.cg.shared.global [%0], [%1], 16;" :: "r"(d), "l"(src));
}
#define CP_COMMIT() asm volatile("cp.async.commit_group;" ::: "memory")
#define CP_WAIT1()  asm volatile("cp.async.wait_group 1;" ::: "memory")

#define MMA_BF16(d, a, b0_, b1_)                                                  \
    asm volatile("mma.sync.aligned.m16n8k16.row.col.f32.bf16.bf16.f32 "           \
                 "{%0,%1,%2,%3}, {%4,%5,%6,%7}, {%8,%9}, {%0,%1,%2,%3};"          \
                 : "+f"((d)[0]), "+f"((d)[1]), "+f"((d)[2]), "+f"((d)[3])         \
                 : "r"((a)[0]), "r"((a)[1]), "r"((a)[2]), "r"((a)[3]),            \
                   "r"(b0_), "r"(b1_))

__device__ __forceinline__ uint32_t packbf(float x, float y) {
    __nv_bfloat162 h = __floats2bfloat162_rn(x, y);
    uint32_t u; memcpy(&u, &h, 4); return u;
}

__device__ __forceinline__ void stage_em(const float* __restrict__ em, float* dst,
                                         int T0, int st, int tid) {
    #pragma unroll
    for (int it = 0; it < 8; it++) {
        int q = tid + it * THREADS;
        int n = q >> 5, c = q & 31;
        int t = T0 + n * CHUNK + st;
        if (t < 0) t = 0;
        if (t > SEQ_LEN - 1) t = SEQ_LEN - 1;
        cp16(dst + n * EMSTRIDE + c * 4, em + (size_t)t * NT + c * 4);
    }
}

__global__ void __launch_bounds__(THREADS, 1)
crf_main(const float* __restrict__ em, const int* __restrict__ tags,
         const int* __restrict__ w2w, const float* __restrict__ trans_g,
         const float* __restrict__ tu2s, const float* __restrict__ ts2u,
         float* __restrict__ out)
{
    extern __shared__ __align__(16) char smem[];
    float*  invsm   = (float*)(smem + SM_INV);
    float*  fpartsm = (float*)(smem + SM_FPART);
    float*  lamsm   = (float*)(smem + SM_LAM);
    float*  redsm   = (float*)(smem + SM_RED);
    double* sgold   = (double*)(smem + SM_SGOLD);
    unsigned char* selbuf = (unsigned char*)(smem + SM_SEL);
    int*    slast   = (int*)(smem + SM_SLAST);

    const int tid  = threadIdx.x, cta = blockIdx.x;
    const int lane = tid & 31, w = tid >> 5;
    const int r    = lane >> 2;
    const int cb   = (lane & 3) * 2;
    const int m0   = w * 16 + r, m1 = m0 + 8;

    /* ===== phase 1: gold path score (fp64, deterministic) ===== */
    double gacc = 0.0;
    for (int t = cta * THREADS + tid; t < SEQ_LEN; t += NCTA * THREADS) {
        int tcur = tags[t];
        gacc += (double)em[(size_t)t * NT + tcur];
        if (t >= 1) {
            int tprev = tags[t - 1];
            const float* tm = (w2w[t] == 0) ? tu2s : ts2u;
            gacc += (double)tm[tprev * NT + tcur];
        }
    }
    #pragma unroll
    for (int o = 16; o; o >>= 1) gacc += __shfl_down_sync(0xffffffffu, gacc, o);
    if (lane == 0) sgold[w] = gacc;
    __syncthreads();
    if (tid == 0) {
        double s = 0.0;
        #pragma unroll
        for (int q = 0; q < 8; q++) s += sgold[q];
        g_gold[cta] = s;
    }

    /* ===== phase 2: A fragments (exp(trans^T)) for both matrices ===== */
    uint32_t A1[8][4], A2[8][4];
    #pragma unroll
    for (int kt = 0; kt < 8; kt++) {
        int kb = kt * 16 + cb;
        A1[kt][0] = packbf(__expf(tu2s[kb * NT + m0]),       __expf(tu2s[(kb + 1) * NT + m0]));
        A1[kt][1] = packbf(__expf(tu2s[kb * NT + m1]),       __expf(tu2s[(kb + 1) * NT + m1]));
        A1[kt][2] = packbf(__expf(tu2s[(kb + 8) * NT + m0]), __expf(tu2s[(kb + 9) * NT + m0]));
        A1[kt][3] = packbf(__expf(tu2s[(kb + 8) * NT + m1]), __expf(tu2s[(kb + 9) * NT + m1]));
        A2[kt][0] = packbf(__expf(ts2u[kb * NT + m0]),       __expf(ts2u[(kb + 1) * NT + m0]));
        A2[kt][1] = packbf(__expf(ts2u[kb * NT + m1]),       __expf(ts2u[(kb + 1) * NT + m1]));
        A2[kt][2] = packbf(__expf(ts2u[(kb + 8) * NT + m0]), __expf(ts2u[(kb + 9) * NT + m0]));
        A2[kt][3] = packbf(__expf(ts2u[(kb + 8) * NT + m1]), __expf(ts2u[(kb + 9) * NT + m1]));
    }

    const int T0 = 1 + cta * (G * CHUNK) - WARM;

    for (int i = tid; i < G * NT; i += THREADS) {
        int n = i >> 7, k = i & 127;
        *(__nv_bfloat16*)(smem + SM_V0 + n * VSTRIDE + k * 2) = __float2bfloat16(1.0f);
    }
    for (int i = tid; i < G; i += THREADS) { invsm[i] = 1.f; fpartsm[i] = 1.f; lamsm[i] = 0.f; }
    for (int i = tid; i < G * STEPS; i += THREADS) {
        int n = i / STEPS, s = i % STEPS;
        int t = T0 + n * CHUNK + s;
        if (t < 0) t = 0;
        if (t > SEQ_LEN - 1) t = SEQ_LEN - 1;
        selbuf[i] = (unsigned char)(w2w[t] != 0);
    }
    stage_em(em, (float*)(smem + SM_EM),            T0, 0, tid); CP_COMMIT();
    stage_em(em, (float*)(smem + SM_EM + EMBYTES),  T0, 1, tid); CP_COMMIT();
    __syncthreads();

    /* ===== phase 3: lockstep scan, 24 steps, 1 barrier/step ===== */
    for (int s = 0; s < STEPS; s++) {
        CP_WAIT1();
        __syncthreads();                 /* em(s) ready; prev stores visible */
        const float* eb   = (const float*)(smem + SM_EM + (s % 3) * EMBYTES);
        const char*  vcur = smem + ((s & 1) ? SM_V1 : SM_V0);
        char*        vnxt = smem + ((s & 1) ? SM_V0 : SM_V1);
        const bool doinv   = (s > 0 && (s & 7) == 0);
        const bool needred = ((s & 7) == 7) || (s == 22 && cta == NCTA - 1);

        float acc1[8][4], acc2[8][4];
        #pragma unroll
        for (int nt = 0; nt < 8; nt++)
            #pragma unroll
            for (int q = 0; q < 4; q++) { acc1[nt][q] = 0.f; acc2[nt][q] = 0.f; }

        #pragma unroll
        for (int kt = 0; kt < 8; kt++) {
            uint32_t b0[8], b1[8];
            #pragma unroll
            for (int nt = 0; nt < 8; nt++) {
                const char* p = vcur + (nt * 8 + r) * VSTRIDE + (kt * 16 + cb) * 2;
                b0[nt] = *(const uint32_t*)p;
                b1[nt] = *(const uint32_t*)(p + 16);
            }
            #pragma unroll
            for (int nt = 0; nt < 8; nt++) {
                MMA_BF16(acc1[nt], A1[kt], b0[nt], b1[nt]);
                MMA_BF16(acc2[nt], A2[kt], b0[nt], b1[nt]);
            }
        }

        #pragma unroll
        for (int nt = 0; nt < 8; nt++) {
            const int n0 = nt * 8 + cb, n1 = n0 + 1;
            const int sel0 = selbuf[n0 * STEPS + s];
            const int sel1 = selbuf[n1 * STEPS + s];
            const int thi0 = min(SEQ_LEN, 1 + (cta * G + n0 + 1) * CHUNK);
            const int thi1 = min(SEQ_LEN, 1 + (cta * G + n1 + 1) * CHUNK);
            const bool a0 = (T0 + n0 * CHUNK + s) < thi0;
            const bool a1 = (T0 + n1 * CHUNK + s) < thi1;
            float e00 = __expf(eb[n0 * EMSTRIDE + m0]);
            float e01 = __expf(eb[n0 * EMSTRIDE + m1]);
            float e10 = __expf(eb[n1 * EMSTRIDE + m0]);
            float e11 = __expf(eb[n1 * EMSTRIDE + m1]);
            float c0 = (sel0 ? acc2[nt][0] : acc1[nt][0]) * e00;
            float c1 = (sel1 ? acc2[nt][1] : acc1[nt][1]) * e10;
            float c2 = (sel0 ? acc2[nt][2] : acc1[nt][2]) * e01;
            float c3 = (sel1 ? acc2[nt][3] : acc1[nt][3]) * e11;
            if (doinv) {
                float i0 = invsm[n0], i1 = invsm[n1];
                c0 *= i0; c2 *= i0; c1 *= i1; c3 *= i1;
            }
            if (s == 7 && cta == 0 && n0 == 0) { c0 = e00; c2 = e01; }  /* seed a(0) */
            if (!a0) { c0 = 0.f; c2 = 0.f; }
            if (!a1) { c1 = 0.f; c3 = 0.f; }
            *(__nv_bfloat16*)(vnxt + n0 * VSTRIDE + m0 * 2) = __float2bfloat16(c0);
            *(__nv_bfloat16*)(vnxt + n0 * VSTRIDE + m1 * 2) = __float2bfloat16(c2);
            *(__nv_bfloat16*)(vnxt + n1 * VSTRIDE + m0 * 2) = __float2bfloat16(c1);
            *(__nv_bfloat16*)(vnxt + n1 * VSTRIDE + m1 * 2) = __float2bfloat16(c3);
            if (needred) {
                float p0 = c0 + c2, p1 = c1 + c3;
                #pragma unroll
                for (int o = 4; o <= 16; o <<= 1) {
                    p0 += __shfl_xor_sync(0xffffffffu, p0, o);
                    p1 += __shfl_xor_sync(0xffffffffu, p1, o);
                }
                if (lane < 4) {
                    redsm[n0 * 8 + w] = p0;
                    redsm[n1 * 8 + w] = p1;
                }
            }
        }

        if (needred) {
            __syncthreads();
            if (tid < G) {
                int n = tid;
                float nm = 0.f;
                #pragma unroll
                for (int q = 0; q < 8; q++) nm += redsm[n * 8 + q];
                if ((s & 7) == 7) {
                    invsm[n] = __fdividef(1.0f, nm);
                    if (s == 7) { if (cta == 0 && n == 0) lamsm[0] += logf(nm); }
                    else if (s == 15) lamsm[n] += logf(nm);
                    else if (!(cta == NCTA - 1 && n == G - 1)) fpartsm[n] = nm;  /* s=23 */
                }
                if (s == 22 && cta == NCTA - 1 && n == G - 1) fpartsm[n] = nm;
            }
        }

        stage_em(em, (float*)(smem + SM_EM + ((s + 2) % 3) * EMBYTES), T0, s + 2, tid);
        CP_COMMIT();
    }
    __syncthreads();

    /* ===== per-CTA total + fused finalize ===== */
    if (tid == 0) {
        double tot = 0.0;
        for (int n = 0; n < G; n++) tot += (double)lamsm[n] + (double)logf(fpartsm[n]);
        g_tot[cta] = tot;
        __threadfence();
        unsigned v = atomicAdd(&g_done, 1u);
        *slast = (v == NCTA - 1) ? 1 : 0;
    }
    __syncthreads();

    if (*slast) {
        __threadfence();
        double g = 0.0, t = 0.0;
        for (int i = tid; i < NCTA; i += THREADS) { g += g_gold[i]; t += g_tot[i]; }
        #pragma unroll
        for (int o = 16; o; o >>= 1) {
            g += __shfl_down_sync(0xffffffffu, g, o);
            t += __shfl_down_sync(0xffffffffu, t, o);
        }
        double* sred = (double*)redsm;
        if (lane == 0) { sgold[w] = g; sred[w] = t; }
        __syncthreads();
        if (tid == 0) {
            double gs = 0.0, ts = 0.0;
            #pragma unroll
            for (int q = 0; q < 8; q++) { gs += sgold[q]; ts += sred[q]; }
            out[0] = (float)gs;
            out[1] = (float)ts;
            g_done = 0;
        }
    }
}

extern "C" void kernel_launch(void* const* d_in, const int* in_sizes, int n_in,
                              void* d_out, int out_size) {
    const float* em   = (const float*)d_in[0];
    const int*   tags = (const int*)d_in[1];
    const int*   w2w  = (const int*)d_in[2];
    const float* tg   = (const float*)d_in[3];
    const float* tu2s = (const float*)d_in[4];
    const float* ts2u = (const float*)d_in[5];
    cudaFuncSetAttribute(crf_main, cudaFuncAttributeMaxDynamicSharedMemorySize, SMEM_TOTAL);
    crf_main<<<NCTA, THREADS, SMEM_TOTAL>>>(em, tags, w2w, tg, tu2s, ts2u, (float*)d_out);
}

// round 15
// speedup vs baseline: 1.0317x; 1.0317x over previous
#include <cuda_runtime.h>
#include <cuda_bf16.h>
#include <cstdint>
#include <cstring>

#define SEQ_LEN  131072
#define NT       128
#define NCTA     128
#define THREADS  512
#define G        32          /* chains per CTA (MMA N) */
#define CHUNK    32          /* official steps per chain */
#define WARM     8
#define STEPS    40
#define VSTRIDE  272         /* bytes per V row (bank-conflict-free) */
#define EMSTRIDE 132         /* floats per em row */
#define EMBYTES  (G * EMSTRIDE * 4)   /* 16896 */

/* dynamic smem layout */
#define SM_V0    0
#define SM_V1    8704
#define SM_EM    17408       /* 3 x EMBYTES */
#define SM_SEL   68096       /* uchar[G*STEPS] = 1280 */
#define SM_INV   69376
#define SM_FPART 69504
#define SM_LAM   69632
#define SM_RED   69760       /* float[G*16] = 2048 */
#define SM_SGOLD 71808       /* double[16] */
#define SM_SLAST 71936
#define SMEM_TOTAL 72704

__device__ double   g_gold[NCTA];
__device__ double   g_tot[NCTA];
__device__ unsigned g_done = 0;

__device__ __forceinline__ void cp16(void* dst, const void* src) {
    unsigned d = (unsigned)__cvta_generic_to_shared(dst);
    asm volatile("cp.async.cg.shared.global [%0], [%1], 16;" :: "r"(d), "l"(src));
}
#define CP_COMMIT() asm volatile("cp.async.commit_group;" ::: "memory")
#define CP_WAIT1()  asm volatile("cp.async.wait_group 1;" ::: "memory")

#define MMA_BF16(d, a, b0_, b1_)                                                  \
    asm volatile("mma.sync.aligned.m16n8k16.row.col.f32.bf16.bf16.f32 "           \
                 "{%0,%1,%2,%3}, {%4,%5,%6,%7}, {%8,%9}, {%0,%1,%2,%3};"          \
                 : "+f"((d)[0]), "+f"((d)[1]), "+f"((d)[2]), "+f"((d)[3])         \
                 : "r"((a)[0]), "r"((a)[1]), "r"((a)[2]), "r"((a)[3]),            \
                   "r"(b0_), "r"(b1_))

__device__ __forceinline__ uint32_t packbf(float x, float y) {
    __nv_bfloat162 h = __floats2bfloat162_rn(x, y);
    uint32_t u; memcpy(&u, &h, 4); return u;
}

__device__ __forceinline__ void stage_em(const float* __restrict__ em, float* dst,
                                         int T0, int st, int tid) {
    #pragma unroll
    for (int it = 0; it < 2; it++) {
        int q = tid + it * THREADS;
        int n = q >> 5, c = q & 31;
        int t = T0 + n * CHUNK + st;
        if (t < 0) t = 0;
        if (t > SEQ_LEN - 1) t = SEQ_LEN - 1;
        cp16(dst + n * EMSTRIDE + c * 4, em + (size_t)t * NT + c * 4);
    }
}

__global__ void __launch_bounds__(THREADS, 1)
crf_main(const float* __restrict__ em, const int* __restrict__ tags,
         const int* __restrict__ w2w, const float* __restrict__ trans_g,
         const float* __restrict__ tu2s, const float* __restrict__ ts2u,
         float* __restrict__ out)
{
    extern __shared__ __align__(16) char smem[];
    float*  invsm   = (float*)(smem + SM_INV);
    float*  fpartsm = (float*)(smem + SM_FPART);
    float*  lamsm   = (float*)(smem + SM_LAM);
    float*  redsm   = (float*)(smem + SM_RED);
    double* sgold   = (double*)(smem + SM_SGOLD);
    unsigned char* selbuf = (unsigned char*)(smem + SM_SEL);
    int*    slast   = (int*)(smem + SM_SLAST);

    const int tid  = threadIdx.x, cta = blockIdx.x;
    const int lane = tid & 31, w = tid >> 5;
    const int grp  = w >> 3;                 /* 0: Ka owner, 1: Kb owner */
    const int wm   = w & 7;
    const int r    = lane >> 2;
    const int cb   = (lane & 3) * 2;
    const int m0   = wm * 16 + r, m1 = m0 + 8;

    /* ===== phase 1: gold path score (fp64, deterministic) ===== */
    double gacc = 0.0;
    for (int t = cta * THREADS + tid; t < SEQ_LEN; t += NCTA * THREADS) {
        int tcur = tags[t];
        gacc += (double)em[(size_t)t * NT + tcur];
        if (t >= 1) {
            int tprev = tags[t - 1];
            const float* tm = (w2w[t] == 0) ? tu2s : ts2u;
            gacc += (double)tm[tprev * NT + tcur];
        }
    }
    #pragma unroll
    for (int o = 16; o; o >>= 1) gacc += __shfl_down_sync(0xffffffffu, gacc, o);
    if (lane == 0) sgold[w] = gacc;
    __syncthreads();
    if (tid == 0) {
        double s = 0.0;
        #pragma unroll
        for (int q = 0; q < 16; q++) s += sgold[q];
        g_gold[cta] = s;
    }

    /* ===== phase 2: A fragments (this group's matrix only) ===== */
    const float* KM = (grp == 0) ? tu2s : ts2u;
    uint32_t A[8][4];
    #pragma unroll
    for (int kt = 0; kt < 8; kt++) {
        int kb = kt * 16 + cb;
        A[kt][0] = packbf(__expf(KM[kb * NT + m0]),       __expf(KM[(kb + 1) * NT + m0]));
        A[kt][1] = packbf(__expf(KM[kb * NT + m1]),       __expf(KM[(kb + 1) * NT + m1]));
        A[kt][2] = packbf(__expf(KM[(kb + 8) * NT + m0]), __expf(KM[(kb + 9) * NT + m0]));
        A[kt][3] = packbf(__expf(KM[(kb + 8) * NT + m1]), __expf(KM[(kb + 9) * NT + m1]));
    }

    const int T0 = 1 + cta * (G * CHUNK) - WARM;

    for (int i = tid; i < G * NT; i += THREADS) {
        int n = i >> 7, k = i & 127;
        *(__nv_bfloat16*)(smem + SM_V0 + n * VSTRIDE + k * 2) = __float2bfloat16(1.0f);
    }
    for (int i = tid; i < G; i += THREADS) { invsm[i] = 1.f; fpartsm[i] = 1.f; lamsm[i] = 0.f; }
    for (int i = tid; i < G * STEPS; i += THREADS) {
        int n = i / STEPS, s = i % STEPS;
        int t = T0 + n * CHUNK + s;
        if (t < 0) t = 0;
        if (t > SEQ_LEN - 1) t = SEQ_LEN - 1;
        selbuf[i] = (unsigned char)(w2w[t] != 0);
    }
    stage_em(em, (float*)(smem + SM_EM),           T0, 0, tid); CP_COMMIT();
    stage_em(em, (float*)(smem + SM_EM + EMBYTES), T0, 1, tid); CP_COMMIT();
    __syncthreads();

    /* ===== phase 3: lockstep scan, 40 steps ===== */
    for (int s = 0; s < STEPS; s++) {
        CP_WAIT1();
        __syncthreads();                 /* em(s) ready; prev stores visible */
        const float* eb   = (const float*)(smem + SM_EM + (s % 3) * EMBYTES);
        const char*  vcur = smem + ((s & 1) ? SM_V1 : SM_V0);
        char*        vnxt = smem + ((s & 1) ? SM_V0 : SM_V1);
        const bool doinv   = (s > 0 && (s & 7) == 0);
        const bool needred = ((s & 7) == 7) || (s == 38 && cta == NCTA - 1);

        float acc[4][4];
        #pragma unroll
        for (int nt = 0; nt < 4; nt++)
            #pragma unroll
            for (int q = 0; q < 4; q++) acc[nt][q] = 0.f;

        #pragma unroll
        for (int kt = 0; kt < 8; kt++) {
            uint32_t b0[4], b1[4];
            #pragma unroll
            for (int nt = 0; nt < 4; nt++) {
                const char* p = vcur + (nt * 8 + r) * VSTRIDE + (kt * 16 + cb) * 2;
                b0[nt] = *(const uint32_t*)p;
                b1[nt] = *(const uint32_t*)(p + 16);
            }
            #pragma unroll
            for (int nt = 0; nt < 4; nt++)
                MMA_BF16(acc[nt], A[kt], b0[nt], b1[nt]);
        }

        #pragma unroll
        for (int nt = 0; nt < 4; nt++) {
            const int n0 = nt * 8 + cb, n1 = n0 + 1;
            const bool own0 = (selbuf[n0 * STEPS + s] == grp);
            const bool own1 = (selbuf[n1 * STEPS + s] == grp);
            const int thi0 = min(SEQ_LEN, 1 + (cta * G + n0 + 1) * CHUNK);
            const int thi1 = min(SEQ_LEN, 1 + (cta * G + n1 + 1) * CHUNK);
            const bool a0 = (T0 + n0 * CHUNK + s) < thi0;
            const bool a1 = (T0 + n1 * CHUNK + s) < thi1;
            float e00 = __expf(eb[n0 * EMSTRIDE + m0]);
            float e01 = __expf(eb[n0 * EMSTRIDE + m1]);
            float e10 = __expf(eb[n1 * EMSTRIDE + m0]);
            float e11 = __expf(eb[n1 * EMSTRIDE + m1]);
            float c0 = acc[nt][0] * e00;     /* (m0,n0) */
            float c1 = acc[nt][1] * e10;     /* (m0,n1) */
            float c2 = acc[nt][2] * e01;     /* (m1,n0) */
            float c3 = acc[nt][3] * e11;     /* (m1,n1) */
            if (doinv) {
                float i0 = invsm[n0], i1 = invsm[n1];
                c0 *= i0; c2 *= i0; c1 *= i1; c3 *= i1;
            }
            if (s == 7 && cta == 0 && n0 == 0) { c0 = e00; c2 = e01; } /* seed a(0) */
            if (!a0) { c0 = 0.f; c2 = 0.f; }
            if (!a1) { c1 = 0.f; c3 = 0.f; }
            if (own0) {      /* owner group stores its columns */
                *(__nv_bfloat16*)(vnxt + n0 * VSTRIDE + m0 * 2) = __float2bfloat16(c0);
                *(__nv_bfloat16*)(vnxt + n0 * VSTRIDE + m1 * 2) = __float2bfloat16(c2);
            }
            if (own1) {
                *(__nv_bfloat16*)(vnxt + n1 * VSTRIDE + m0 * 2) = __float2bfloat16(c1);
                *(__nv_bfloat16*)(vnxt + n1 * VSTRIDE + m1 * 2) = __float2bfloat16(c3);
            }
            if (needred) {
                float p0 = own0 ? (c0 + c2) : 0.f;
                float p1 = own1 ? (c1 + c3) : 0.f;
                #pragma unroll
                for (int o = 4; o <= 16; o <<= 1) {
                    p0 += __shfl_xor_sync(0xffffffffu, p0, o);
                    p1 += __shfl_xor_sync(0xffffffffu, p1, o);
                }
                if (lane < 4) {
                    redsm[n0 * 16 + w] = p0;
                    redsm[n1 * 16 + w] = p1;
                }
            }
        }

        if (needred) {
            __syncthreads();
            if (tid < G) {
                int n = tid;
                float nm = 0.f;
                #pragma unroll
                for (int q = 0; q < 16; q++) nm += redsm[n * 16 + q];
                if ((s & 7) == 7) {
                    invsm[n] = __fdividef(1.0f, nm);
                    if (s == 7) { if (cta == 0 && n == 0) lamsm[0] += logf(nm); }
                    else if (s < 39) lamsm[n] += logf(nm);           /* 15,23,31 */
                    else if (!(cta == NCTA - 1 && n == G - 1)) fpartsm[n] = nm;
                }
                if (s == 38 && cta == NCTA - 1 && n == G - 1) fpartsm[n] = nm;
            }
        }

        stage_em(em, (float*)(smem + SM_EM + ((s + 2) % 3) * EMBYTES), T0, s + 2, tid);
        CP_COMMIT();
    }
    __syncthreads();

    /* ===== per-CTA total + fused finalize ===== */
    if (tid == 0) {
        double tot = 0.0;
        for (int n = 0; n < G; n++) tot += (double)lamsm[n] + (double)logf(fpartsm[n]);
        g_tot[cta] = tot;
        __threadfence();
        unsigned v = atomicAdd(&g_done, 1u);
        *slast = (v == NCTA - 1) ? 1 : 0;
    }
    __syncthreads();

    if (*slast) {
        __threadfence();
        double g = 0.0, t = 0.0;
        for (int i = tid; i < NCTA; i += THREADS) { g += g_gold[i]; t += g_tot[i]; }
        #pragma unroll
        for (int o = 16; o; o >>= 1) {
            g += __shfl_down_sync(0xffffffffu, g, o);
            t += __shfl_down_sync(0xffffffffu, t, o);
        }
        double* sred = (double*)redsm;
        if (lane == 0) { sgold[w] = g; sred[w] = t; }
        __syncthreads();
        if (tid == 0) {
            double gs = 0.0, ts = 0.0;
            #pragma unroll
            for (int q = 0; q < 16; q++) { gs += sgold[q]; ts += sred[q]; }
            out[0] = (float)gs;
            out[1] = (float)ts;
            g_done = 0;
        }
    }
}

extern "C" void kernel_launch(void* const* d_in, const int* in_sizes, int n_in,
                              void* d_out, int out_size) {
    const float* em   = (const float*)d_in[0];
    const int*   tags = (const int*)d_in[1];
    const int*   w2w  = (const int*)d_in[2];
    const float* tg   = (const float*)d_in[3];
    const float* tu2s = (const float*)d_in[4];
    const float* ts2u = (const float*)d_in[5];
    cudaFuncSetAttribute(crf_main, cudaFuncAttributeMaxDynamicSharedMemorySize, SMEM_TOTAL);
    crf_main<<<NCTA, THREADS, SMEM_TOTAL>>>(em, tags, w2w, tg, tu2s, ts2u, (float*)d_out);
}

// round 16
// speedup vs baseline: 1.2728x; 1.2338x over previous
#include <cuda_runtime.h>
#include <cuda_bf16.h>
#include <cstdint>
#include <cstring>

#define SEQ_LEN  131072
#define NT       128
#define NCTA     128
#define THREADS  512
#define G        32          /* chains per CTA (MMA N) */
#define CHUNK    32          /* official steps per chain */
#define WARM     8
#define STEPS    40
#define VSTRIDE  272         /* bytes per V row (bank-conflict-free) */
#define EMSTRIDE 132         /* floats per em row */
#define EMBYTES  (G * EMSTRIDE * 4)   /* 16896 */

/* dynamic smem layout */
#define SM_V0    0
#define SM_V1    8704
#define SM_EM    17408       /* 3 x EMBYTES -> ends 68096 */
#define SM_SELW  68096       /* uint32[STEPS] = 160 */
#define SM_INV   68256
#define SM_FPART 68384
#define SM_LAM   68512
#define SM_RED   68640       /* float[G*8] = 1024 */
#define SM_SGOLD 69664       /* double[16] = 128 */
#define SM_SLAST 69792
#define SMEM_TOTAL 69888

__device__ double   g_gold[NCTA];
__device__ double   g_tot[NCTA];
__device__ unsigned g_done = 0;

__device__ __forceinline__ void cp16(void* dst, const void* src) {
    unsigned d = (unsigned)__cvta_generic_to_shared(dst);
    asm volatile("cp.async.cg.shared.global [%0], [%1], 16;" :: "r"(d), "l"(src));
}
#define CP_COMMIT() asm volatile("cp.async.commit_group;" ::: "memory")
#define CP_WAIT1()  asm volatile("cp.async.wait_group 1;" ::: "memory")

#define MMA_BF16(d, a, b0_, b1_)                                                  \
    asm volatile("mma.sync.aligned.m16n8k16.row.col.f32.bf16.bf16.f32 "           \
                 "{%0,%1,%2,%3}, {%4,%5,%6,%7}, {%8,%9}, {%0,%1,%2,%3};"          \
                 : "+f"((d)[0]), "+f"((d)[1]), "+f"((d)[2]), "+f"((d)[3])         \
                 : "r"((a)[0]), "r"((a)[1]), "r"((a)[2]), "r"((a)[3]),            \
                   "r"(b0_), "r"(b1_))

__device__ __forceinline__ uint32_t packbf(float x, float y) {
    __nv_bfloat162 h = __floats2bfloat162_rn(x, y);
    uint32_t u; memcpy(&u, &h, 4); return u;
}

__device__ __forceinline__ void stage_em(const float* __restrict__ em, float* dst,
                                         int T0, int st, int tid) {
    #pragma unroll
    for (int it = 0; it < 2; it++) {
        int q = tid + it * THREADS;
        int n = q >> 5, c = q & 31;
        int t = T0 + n * CHUNK + st;
        if (t < 0) t = 0;
        if (t > SEQ_LEN - 1) t = SEQ_LEN - 1;
        cp16(dst + n * EMSTRIDE + c * 4, em + (size_t)t * NT + c * 4);
    }
}

__global__ void __launch_bounds__(THREADS, 1)
crf_main(const float* __restrict__ em, const int* __restrict__ tags,
         const int* __restrict__ w2w, const float* __restrict__ trans_g,
         const float* __restrict__ tu2s, const float* __restrict__ ts2u,
         float* __restrict__ out)
{
    extern __shared__ __align__(16) char smem[];
    float*    invsm   = (float*)(smem + SM_INV);
    float*    fpartsm = (float*)(smem + SM_FPART);
    float*    lamsm   = (float*)(smem + SM_LAM);
    float*    redsm   = (float*)(smem + SM_RED);
    double*   sgold   = (double*)(smem + SM_SGOLD);
    uint32_t* selw    = (uint32_t*)(smem + SM_SELW);
    int*      slast   = (int*)(smem + SM_SLAST);

    const int tid  = threadIdx.x, cta = blockIdx.x;
    const int lane = tid & 31, w = tid >> 5;
    const int grp  = w >> 3;                 /* column half: 0 -> n 0..15, 1 -> n 16..31 */
    const int wm   = w & 7;
    const int r    = lane >> 2;
    const int cb   = (lane & 3) * 2;
    const int m0   = wm * 16 + r, m1 = m0 + 8;
    const int nbase = grp * 16;

    /* ===== phase 1: gold path score (fp64, deterministic) ===== */
    double gacc = 0.0;
    for (int t = cta * THREADS + tid; t < SEQ_LEN; t += NCTA * THREADS) {
        int tcur = tags[t];
        gacc += (double)em[(size_t)t * NT + tcur];
        if (t >= 1) {
            int tprev = tags[t - 1];
            const float* tm = (w2w[t] == 0) ? tu2s : ts2u;
            gacc += (double)tm[tprev * NT + tcur];
        }
    }
    #pragma unroll
    for (int o = 16; o; o >>= 1) gacc += __shfl_down_sync(0xffffffffu, gacc, o);
    if (lane == 0) sgold[w] = gacc;
    __syncthreads();
    if (tid == 0) {
        double s = 0.0;
        #pragma unroll
        for (int q = 0; q < 16; q++) s += sgold[q];
        g_gold[cta] = s;
    }

    /* ===== phase 2: A fragments for BOTH matrices (rows m0/m1) ===== */
    uint32_t A1[8][4], A2[8][4];
    #pragma unroll
    for (int kt = 0; kt < 8; kt++) {
        int kb = kt * 16 + cb;
        A1[kt][0] = packbf(__expf(tu2s[kb * NT + m0]),       __expf(tu2s[(kb + 1) * NT + m0]));
        A1[kt][1] = packbf(__expf(tu2s[kb * NT + m1]),       __expf(tu2s[(kb + 1) * NT + m1]));
        A1[kt][2] = packbf(__expf(tu2s[(kb + 8) * NT + m0]), __expf(tu2s[(kb + 9) * NT + m0]));
        A1[kt][3] = packbf(__expf(tu2s[(kb + 8) * NT + m1]), __expf(tu2s[(kb + 9) * NT + m1]));
        A2[kt][0] = packbf(__expf(ts2u[kb * NT + m0]),       __expf(ts2u[(kb + 1) * NT + m0]));
        A2[kt][1] = packbf(__expf(ts2u[kb * NT + m1]),       __expf(ts2u[(kb + 1) * NT + m1]));
        A2[kt][2] = packbf(__expf(ts2u[(kb + 8) * NT + m0]), __expf(ts2u[(kb + 9) * NT + m0]));
        A2[kt][3] = packbf(__expf(ts2u[(kb + 8) * NT + m1]), __expf(ts2u[(kb + 9) * NT + m1]));
    }

    const int T0 = 1 + cta * (G * CHUNK) - WARM;

    for (int i = tid; i < G * NT; i += THREADS) {
        int n = i >> 7, k = i & 127;
        *(__nv_bfloat16*)(smem + SM_V0 + n * VSTRIDE + k * 2) = __float2bfloat16(1.0f);
    }
    for (int i = tid; i < G; i += THREADS) { invsm[i] = 1.f; fpartsm[i] = 1.f; lamsm[i] = 0.f; }
    if (tid < STEPS) {
        uint32_t word = 0;
        for (int n = 0; n < G; n++) {
            int t = T0 + n * CHUNK + tid;
            if (t < 0) t = 0;
            if (t > SEQ_LEN - 1) t = SEQ_LEN - 1;
            if (w2w[t] != 0) word |= (1u << n);
        }
        selw[tid] = word;
    }
    stage_em(em, (float*)(smem + SM_EM),           T0, 0, tid); CP_COMMIT();
    stage_em(em, (float*)(smem + SM_EM + EMBYTES), T0, 1, tid); CP_COMMIT();
    __syncthreads();

    /* ===== phase 3: lockstep scan, 40 steps, 1 barrier/step ===== */
    for (int s = 0; s < STEPS; s++) {
        CP_WAIT1();
        __syncthreads();                 /* em(s) ready; prev stores visible */
        const float* eb   = (const float*)(smem + SM_EM + (s % 3) * EMBYTES);
        const char*  vcur = smem + ((s & 1) ? SM_V1 : SM_V0);
        char*        vnxt = smem + ((s & 1) ? SM_V0 : SM_V1);
        const bool doinv   = (s > 0 && (s & 7) == 0);
        const bool needred = ((s & 7) == 7) || (s == 38 && cta == NCTA - 1);
        const uint32_t sw  = selw[s];

        float acc1[2][4], acc2[2][4];
        #pragma unroll
        for (int ntl = 0; ntl < 2; ntl++)
            #pragma unroll
            for (int q = 0; q < 4; q++) { acc1[ntl][q] = 0.f; acc2[ntl][q] = 0.f; }

        #pragma unroll
        for (int kt = 0; kt < 8; kt++) {
            uint32_t b0[2], b1[2];
            #pragma unroll
            for (int ntl = 0; ntl < 2; ntl++) {
                const char* p = vcur + (nbase + ntl * 8 + r) * VSTRIDE + (kt * 16 + cb) * 2;
                b0[ntl] = *(const uint32_t*)p;
                b1[ntl] = *(const uint32_t*)(p + 16);
            }
            #pragma unroll
            for (int ntl = 0; ntl < 2; ntl++) {
                MMA_BF16(acc1[ntl], A1[kt], b0[ntl], b1[ntl]);
                MMA_BF16(acc2[ntl], A2[kt], b0[ntl], b1[ntl]);
            }
        }

        #pragma unroll
        for (int ntl = 0; ntl < 2; ntl++) {
            const int n0 = nbase + ntl * 8 + cb, n1 = n0 + 1;
            const bool sel0 = (sw >> n0) & 1;
            const bool sel1 = (sw >> n1) & 1;
            float e00 = __expf(eb[n0 * EMSTRIDE + m0]);
            float e01 = __expf(eb[n0 * EMSTRIDE + m1]);
            float e10 = __expf(eb[n1 * EMSTRIDE + m0]);
            float e11 = __expf(eb[n1 * EMSTRIDE + m1]);
            float c0 = (sel0 ? acc2[ntl][0] : acc1[ntl][0]) * e00;   /* (m0,n0) */
            float c1 = (sel1 ? acc2[ntl][1] : acc1[ntl][1]) * e10;   /* (m0,n1) */
            float c2 = (sel0 ? acc2[ntl][2] : acc1[ntl][2]) * e01;   /* (m1,n0) */
            float c3 = (sel1 ? acc2[ntl][3] : acc1[ntl][3]) * e11;   /* (m1,n1) */
            if (doinv) {
                float i0 = invsm[n0], i1 = invsm[n1];
                c0 *= i0; c2 *= i0; c1 *= i1; c3 *= i1;
            }
            if (s == 7 && cta == 0 && n0 == 0) { c0 = e00; c2 = e01; }  /* seed a(0) */
            *(__nv_bfloat16*)(vnxt + n0 * VSTRIDE + m0 * 2) = __float2bfloat16(c0);
            *(__nv_bfloat16*)(vnxt + n0 * VSTRIDE + m1 * 2) = __float2bfloat16(c2);
            *(__nv_bfloat16*)(vnxt + n1 * VSTRIDE + m0 * 2) = __float2bfloat16(c1);
            *(__nv_bfloat16*)(vnxt + n1 * VSTRIDE + m1 * 2) = __float2bfloat16(c3);
            if (needred) {
                float p0 = c0 + c2, p1 = c1 + c3;
                #pragma unroll
                for (int o = 4; o <= 16; o <<= 1) {
                    p0 += __shfl_xor_sync(0xffffffffu, p0, o);
                    p1 += __shfl_xor_sync(0xffffffffu, p1, o);
                }
                if (lane < 4) {
                    redsm[n0 * 8 + wm] = p0;
                    redsm[n1 * 8 + wm] = p1;
                }
            }
        }

        if (needred) {
            __syncthreads();
            if (tid < G) {
                int n = tid;
                float nm = 0.f;
                #pragma unroll
                for (int q = 0; q < 8; q++) nm += redsm[n * 8 + q];
                if ((s & 7) == 7) {
                    invsm[n] = __fdividef(1.0f, nm);
                    if (s == 7) { if (cta == 0 && n == 0) lamsm[0] += logf(nm); }
                    else if (s < 39) lamsm[n] += logf(nm);           /* 15,23,31 */
                    else if (!(cta == NCTA - 1 && n == G - 1)) fpartsm[n] = nm;
                }
                if (s == 38 && cta == NCTA - 1 && n == G - 1) fpartsm[n] = nm;
            }
        }

        stage_em(em, (float*)(smem + SM_EM + ((s + 2) % 3) * EMBYTES), T0, s + 2, tid);
        CP_COMMIT();
    }
    __syncthreads();

    /* ===== per-CTA total + fused finalize ===== */
    if (tid == 0) {
        double tot = 0.0;
        for (int n = 0; n < G; n++) tot += (double)lamsm[n] + (double)logf(fpartsm[n]);
        g_tot[cta] = tot;
        __threadfence();
        unsigned v = atomicAdd(&g_done, 1u);
        *slast = (v == NCTA - 1) ? 1 : 0;
    }
    __syncthreads();

    if (*slast) {
        __threadfence();
        double g = 0.0, t = 0.0;
        for (int i = tid; i < NCTA; i += THREADS) { g += g_gold[i]; t += g_tot[i]; }
        #pragma unroll
        for (int o = 16; o; o >>= 1) {
            g += __shfl_down_sync(0xffffffffu, g, o);
            t += __shfl_down_sync(0xffffffffu, t, o);
        }
        double* sred = (double*)redsm;
        if (lane == 0) { sgold[w] = g; sred[w] = t; }
        __syncthreads();
        if (tid == 0) {
            double gs = 0.0, ts = 0.0;
            #pragma unroll
            for (int q = 0; q < 16; q++) { gs += sgold[q]; ts += sred[q]; }
            out[0] = (float)gs;
            out[1] = (float)ts;
            g_done = 0;
        }
    }
}

extern "C" void kernel_launch(void* const* d_in, const int* in_sizes, int n_in,
                              void* d_out, int out_size) {
    const float* em   = (const float*)d_in[0];
    const int*   tags = (const int*)d_in[1];
    const int*   w2w  = (const int*)d_in[2];
    const float* tg   = (const float*)d_in[3];
    const float* tu2s = (const float*)d_in[4];
    const float* ts2u = (const float*)d_in[5];
    cudaFuncSetAttribute(crf_main, cudaFuncAttributeMaxDynamicSharedMemorySize, SMEM_TOTAL);
    crf_main<<<NCTA, THREADS, SMEM_TOTAL>>>(em, tags, w2w, tg, tu2s, ts2u, (float*)d_out);
}

// round 17
// speedup vs baseline: 1.3391x; 1.0521x over previous
#include <cuda_runtime.h>
#include <cuda_bf16.h>
#include <cstdint>
#include <cstring>

#define SEQ_LEN  131072
#define NT       128
#define NCTA     256
#define THREADS  256
#define G        32          /* chains per CTA (MMA N) */
#define CHUNK    16          /* official steps per chain */
#define WARM     4
#define STEPS    20
#define VSTRIDE  272         /* bytes per V row (bank-conflict-free) */
#define EMSTRIDE 132         /* floats per em row */
#define EMBYTES  (G * EMSTRIDE * 4)   /* 16896 */

/* dynamic smem layout */
#define SM_V0    0
#define SM_V1    8704
#define SM_EM    17408       /* 3 x EMBYTES -> ends 68096 */
#define SM_SELW  68096       /* uint32[STEPS] = 80 */
#define SM_INV   68176
#define SM_FPART 68304
#define SM_LAM   68432
#define SM_RED   68560       /* float[G*8] = 1024 */
#define SM_SGOLD 69584       /* double[8] */
#define SM_SLAST 69648
#define SMEM_TOTAL 69888

__device__ double   g_gold[NCTA];
__device__ double   g_tot[NCTA];
__device__ unsigned g_done = 0;

__device__ __forceinline__ void cp16(void* dst, const void* src) {
    unsigned d = (unsigned)__cvta_generic_to_shared(dst);
    asm volatile("cp.async.cg.shared.global [%0], [%1], 16;" :: "r"(d), "l"(src));
}
#define CP_COMMIT() asm volatile("cp.async.commit_group;" ::: "memory")
#define CP_WAIT1()  asm volatile("cp.async.wait_group 1;" ::: "memory")

#define MMA_BF16(d, a, b0_, b1_)                                                  \
    asm volatile("mma.sync.aligned.m16n8k16.row.col.f32.bf16.bf16.f32 "           \
                 "{%0,%1,%2,%3}, {%4,%5,%6,%7}, {%8,%9}, {%0,%1,%2,%3};"          \
                 : "+f"((d)[0]), "+f"((d)[1]), "+f"((d)[2]), "+f"((d)[3])         \
                 : "r"((a)[0]), "r"((a)[1]), "r"((a)[2]), "r"((a)[3]),            \
                   "r"(b0_), "r"(b1_))

__device__ __forceinline__ uint32_t packbf(float x, float y) {
    __nv_bfloat162 h = __floats2bfloat162_rn(x, y);
    uint32_t u; memcpy(&u, &h, 4); return u;
}

__device__ __forceinline__ void stage_em(const float* __restrict__ em, float* dst,
                                         int T0, int st, int tid) {
    #pragma unroll
    for (int it = 0; it < 4; it++) {
        int q = tid + it * THREADS;
        int n = q >> 5, c = q & 31;
        int t = T0 + n * CHUNK + st;
        if (t < 0) t = 0;
        if (t > SEQ_LEN - 1) t = SEQ_LEN - 1;
        cp16(dst + n * EMSTRIDE + c * 4, em + (size_t)t * NT + c * 4);
    }
}

__global__ void __launch_bounds__(THREADS, 2)
crf_main(const float* __restrict__ em, const int* __restrict__ tags,
         const int* __restrict__ w2w, const float* __restrict__ trans_g,
         const float* __restrict__ tu2s, const float* __restrict__ ts2u,
         float* __restrict__ out)
{
    extern __shared__ __align__(16) char smem[];
    float*    invsm   = (float*)(smem + SM_INV);
    float*    fpartsm = (float*)(smem + SM_FPART);
    float*    lamsm   = (float*)(smem + SM_LAM);
    float*    redsm   = (float*)(smem + SM_RED);
    double*   sgold   = (double*)(smem + SM_SGOLD);
    uint32_t* selw    = (uint32_t*)(smem + SM_SELW);
    int*      slast   = (int*)(smem + SM_SLAST);

    const int tid  = threadIdx.x, cta = blockIdx.x;
    const int lane = tid & 31, w = tid >> 5;
    const int r    = lane >> 2;
    const int cb   = (lane & 3) * 2;
    const int m0   = w * 16 + r, m1 = m0 + 8;

    /* ===== phase 1: gold path score (fp64, deterministic) ===== */
    double gacc = 0.0;
    for (int t = cta * THREADS + tid; t < SEQ_LEN; t += NCTA * THREADS) {
        int tcur = tags[t];
        gacc += (double)em[(size_t)t * NT + tcur];
        if (t >= 1) {
            int tprev = tags[t - 1];
            const float* tm = (w2w[t] == 0) ? tu2s : ts2u;
            gacc += (double)tm[tprev * NT + tcur];
        }
    }
    #pragma unroll
    for (int o = 16; o; o >>= 1) gacc += __shfl_down_sync(0xffffffffu, gacc, o);
    if (lane == 0) sgold[w] = gacc;
    __syncthreads();
    if (tid == 0) {
        double s = 0.0;
        #pragma unroll
        for (int q = 0; q < 8; q++) s += sgold[q];
        g_gold[cta] = s;
    }

    /* ===== phase 2: A fragments for BOTH matrices (rows m0/m1) ===== */
    uint32_t A1[8][4], A2[8][4];
    #pragma unroll
    for (int kt = 0; kt < 8; kt++) {
        int kb = kt * 16 + cb;
        A1[kt][0] = packbf(__expf(tu2s[kb * NT + m0]),       __expf(tu2s[(kb + 1) * NT + m0]));
        A1[kt][1] = packbf(__expf(tu2s[kb * NT + m1]),       __expf(tu2s[(kb + 1) * NT + m1]));
        A1[kt][2] = packbf(__expf(tu2s[(kb + 8) * NT + m0]), __expf(tu2s[(kb + 9) * NT + m0]));
        A1[kt][3] = packbf(__expf(tu2s[(kb + 8) * NT + m1]), __expf(tu2s[(kb + 9) * NT + m1]));
        A2[kt][0] = packbf(__expf(ts2u[kb * NT + m0]),       __expf(ts2u[(kb + 1) * NT + m0]));
        A2[kt][1] = packbf(__expf(ts2u[kb * NT + m1]),       __expf(ts2u[(kb + 1) * NT + m1]));
        A2[kt][2] = packbf(__expf(ts2u[(kb + 8) * NT + m0]), __expf(ts2u[(kb + 9) * NT + m0]));
        A2[kt][3] = packbf(__expf(ts2u[(kb + 8) * NT + m1]), __expf(ts2u[(kb + 9) * NT + m1]));
    }

    const int T0 = 1 + cta * (G * CHUNK) - WARM;

    for (int i = tid; i < G * NT; i += THREADS) {
        int n = i >> 7, k = i & 127;
        *(__nv_bfloat16*)(smem + SM_V0 + n * VSTRIDE + k * 2) = __float2bfloat16(1.0f);
    }
    for (int i = tid; i < G; i += THREADS) { invsm[i] = 1.f; fpartsm[i] = 1.f; lamsm[i] = 0.f; }
    if (tid < STEPS) {
        uint32_t word = 0;
        for (int n = 0; n < G; n++) {
            int t = T0 + n * CHUNK + tid;
            if (t < 0) t = 0;
            if (t > SEQ_LEN - 1) t = SEQ_LEN - 1;
            if (w2w[t] != 0) word |= (1u << n);
        }
        selw[tid] = word;
    }
    stage_em(em, (float*)(smem + SM_EM),           T0, 0, tid); CP_COMMIT();
    stage_em(em, (float*)(smem + SM_EM + EMBYTES), T0, 1, tid); CP_COMMIT();
    __syncthreads();

    /* ===== phase 3: lockstep scan, 20 steps ===== */
    for (int s = 0; s < STEPS; s++) {
        CP_WAIT1();
        __syncthreads();                 /* em(s) ready; prev stores visible */
        const float* eb   = (const float*)(smem + SM_EM + (s % 3) * EMBYTES);
        const char*  vcur = smem + ((s & 1) ? SM_V1 : SM_V0);
        char*        vnxt = smem + ((s & 1) ? SM_V0 : SM_V1);
        const bool doinv   = ((s & 7) == 4);                 /* s = 4, 12 */
        const bool needred = ((s & 7) == 3) || (s == 18 && cta == NCTA - 1);
        const uint32_t sw  = selw[s];

        float acc1[4][4], acc2[4][4];
        #pragma unroll
        for (int ntl = 0; ntl < 4; ntl++)
            #pragma unroll
            for (int q = 0; q < 4; q++) { acc1[ntl][q] = 0.f; acc2[ntl][q] = 0.f; }

        #pragma unroll
        for (int kt = 0; kt < 8; kt++) {
            uint32_t b0[4], b1[4];
            #pragma unroll
            for (int ntl = 0; ntl < 4; ntl++) {
                const char* p = vcur + (ntl * 8 + r) * VSTRIDE + (kt * 16 + cb) * 2;
                b0[ntl] = *(const uint32_t*)p;
                b1[ntl] = *(const uint32_t*)(p + 16);
            }
            #pragma unroll
            for (int ntl = 0; ntl < 4; ntl++) {
                MMA_BF16(acc1[ntl], A1[kt], b0[ntl], b1[ntl]);
                MMA_BF16(acc2[ntl], A2[kt], b0[ntl], b1[ntl]);
            }
        }

        #pragma unroll
        for (int ntl = 0; ntl < 4; ntl++) {
            const int n0 = ntl * 8 + cb, n1 = n0 + 1;
            const bool sel0 = (sw >> n0) & 1;
            const bool sel1 = (sw >> n1) & 1;
            float e00 = __expf(eb[n0 * EMSTRIDE + m0]);
            float e01 = __expf(eb[n0 * EMSTRIDE + m1]);
            float e10 = __expf(eb[n1 * EMSTRIDE + m0]);
            float e11 = __expf(eb[n1 * EMSTRIDE + m1]);
            float c0 = (sel0 ? acc2[ntl][0] : acc1[ntl][0]) * e00;   /* (m0,n0) */
            float c1 = (sel1 ? acc2[ntl][1] : acc1[ntl][1]) * e10;   /* (m0,n1) */
            float c2 = (sel0 ? acc2[ntl][2] : acc1[ntl][2]) * e01;   /* (m1,n0) */
            float c3 = (sel1 ? acc2[ntl][3] : acc1[ntl][3]) * e11;   /* (m1,n1) */
            if (doinv) {
                float i0 = invsm[n0], i1 = invsm[n1];
                c0 *= i0; c2 *= i0; c1 *= i1; c3 *= i1;
            }
            if (s == 3 && cta == 0 && n0 == 0) { c0 = e00; c2 = e01; }  /* seed a(0) */
            *(__nv_bfloat16*)(vnxt + n0 * VSTRIDE + m0 * 2) = __float2bfloat16(c0);
            *(__nv_bfloat16*)(vnxt + n0 * VSTRIDE + m1 * 2) = __float2bfloat16(c2);
            *(__nv_bfloat16*)(vnxt + n1 * VSTRIDE + m0 * 2) = __float2bfloat16(c1);
            *(__nv_bfloat16*)(vnxt + n1 * VSTRIDE + m1 * 2) = __float2bfloat16(c3);
            if (needred) {
                float p0 = c0 + c2, p1 = c1 + c3;
                #pragma unroll
                for (int o = 4; o <= 16; o <<= 1) {
                    p0 += __shfl_xor_sync(0xffffffffu, p0, o);
                    p1 += __shfl_xor_sync(0xffffffffu, p1, o);
                }
                if (lane < 4) {
                    redsm[n0 * 8 + w] = p0;
                    redsm[n1 * 8 + w] = p1;
                }
            }
        }

        if (needred) {
            __syncthreads();
            if (tid < G) {
                int n = tid;
                float nm = 0.f;
                #pragma unroll
                for (int q = 0; q < 8; q++) nm += redsm[n * 8 + q];
                if ((s & 7) == 3) {
                    invsm[n] = __fdividef(1.0f, nm);
                    if (s == 3) { if (cta == 0 && n == 0) lamsm[0] += logf(nm); }
                    else if (s == 11) lamsm[n] += logf(nm);
                    else if (!(cta == NCTA - 1 && n == G - 1)) fpartsm[n] = nm;  /* s=19 */
                }
                if (s == 18 && cta == NCTA - 1 && n == G - 1) fpartsm[n] = nm;
            }
        }

        stage_em(em, (float*)(smem + SM_EM + ((s + 2) % 3) * EMBYTES), T0, s + 2, tid);
        CP_COMMIT();
    }
    __syncthreads();

    /* ===== per-CTA total + fused finalize ===== */
    if (tid == 0) {
        double tot = 0.0;
        for (int n = 0; n < G; n++) tot += (double)lamsm[n] + (double)logf(fpartsm[n]);
        g_tot[cta] = tot;
        __threadfence();
        unsigned v = atomicAdd(&g_done, 1u);
        *slast = (v == NCTA - 1) ? 1 : 0;
    }
    __syncthreads();

    if (*slast) {
        __threadfence();
        double g = 0.0, t = 0.0;
        for (int i = tid; i < NCTA; i += THREADS) { g += g_gold[i]; t += g_tot[i]; }
        #pragma unroll
        for (int o = 16; o; o >>= 1) {
            g += __shfl_down_sync(0xffffffffu, g, o);
            t += __shfl_down_sync(0xffffffffu, t, o);
        }
        double* sred = (double*)redsm;
        if (lane == 0) { sgold[w] = g; sred[w] = t; }
        __syncthreads();
        if (tid == 0) {
            double gs = 0.0, ts = 0.0;
            #pragma unroll
            for (int q = 0; q < 8; q++) { gs += sgold[q]; ts += sred[q]; }
            out[0] = (float)gs;
            out[1] = (float)ts;
            g_done = 0;
        }
    }
}

extern "C" void kernel_launch(void* const* d_in, const int* in_sizes, int n_in,
                              void* d_out, int out_size) {
    const float* em   = (const float*)d_in[0];
    const int*   tags = (const int*)d_in[1];
    const int*   w2w  = (const int*)d_in[2];
    const float* tg   = (const float*)d_in[3];
    const float* tu2s = (const float*)d_in[4];
    const float* ts2u = (const float*)d_in[5];
    cudaFuncSetAttribute(crf_main, cudaFuncAttributeMaxDynamicSharedMemorySize, SMEM_TOTAL);
    crf_main<<<NCTA, THREADS, SMEM_TOTAL>>>(em, tags, w2w, tg, tu2s, ts2u, (float*)d_out);
}